// round 14
// baseline (speedup 1.0000x reference)
#include <cuda_runtime.h>
#include <cuda_bf16.h>
#include <cstdint>

#define BQ 4
#define NN 4096
#define DM 512
#define LP 4104   // ceil(4096/12)*12
#define NROWS (BQ*LP)
#define NSPLIT 24
#define LQS (LP/NSPLIT)   // 171 keys per split
#define HQ (LP/2)         // 2052
#define GEMM_TILES 512
#define GEMM_GRID 296     // 2 CTAs/SM * 148 SMs

// ---------------- scratch (device globals) ----------------
__device__ __nv_bfloat16 g_Yh[(size_t)BQ*NN*DM];   // conv output hi
__device__ __nv_bfloat16 g_Yl[(size_t)BQ*NN*DM];   // conv output lo
__device__ __nv_bfloat16 g_Wh[DM*DM];              // pw_w hi
__device__ __nv_bfloat16 g_Wl[DM*DM];              // pw_w lo
__device__ float g_Y2[(size_t)BQ*LP*DM];           // pointwise output
__device__ float g_T [NROWS];                      // per-position score dot (atomic)
__device__ float g_S [NROWS*4];                    // softmaxed block scores
__device__ float4 g_Pa[NSPLIT][NROWS];             // attention partial numerators

// ---------------- f32x2 packed helpers ----------------
__device__ __forceinline__ unsigned long long mul2(unsigned long long a, unsigned long long b) {
    unsigned long long d;
    asm("mul.rn.f32x2 %0, %1, %2;" : "=l"(d) : "l"(a), "l"(b));
    return d;
}
__device__ __forceinline__ unsigned long long fma2(unsigned long long a, unsigned long long b,
                                                   unsigned long long c) {
    unsigned long long d;
    asm("fma.rn.f32x2 %0, %1, %2, %3;" : "=l"(d) : "l"(a), "l"(b), "l"(c));
    return d;
}
__device__ __forceinline__ unsigned long long pack2(float lo, float hi) {
    unsigned long long d;
    asm("mov.b64 %0, {%1, %2};" : "=l"(d) : "f"(lo), "f"(hi));
    return d;
}
__device__ __forceinline__ void unpack2(unsigned long long v, float& lo, float& hi) {
    asm("mov.b64 {%0, %1}, %2;" : "=f"(lo), "=f"(hi) : "l"(v));
}

// ---------------- conv (+ fused prep: W split, T zero, Y2 pad zero) ----------------
__global__ void __launch_bounds__(128) k_conv(const int* __restrict__ x,
                                              const float* __restrict__ emb,
                                              const float* __restrict__ dww,
                                              const float* __restrict__ dwb,
                                              const float* __restrict__ W) {
    // fused prep: 2048 blocks * 128 threads = 262144 = DM*DM exactly
    int gidx = (blockIdx.y * gridDim.x + blockIdx.x) * 128 + threadIdx.x;
    {
        float w = W[gidx];
        __nv_bfloat16 h = __float2bfloat16(w);
        g_Wh[gidx] = h;
        g_Wl[gidx] = __float2bfloat16(w - __bfloat162float(h));
    }
    if (gidx < NROWS) g_T[gidx] = 0.0f;
    if (gidx < BQ * 8 * DM) {
        int bb = gidx / (8 * DM);
        int r = gidx % (8 * DM);
        g_Y2[((size_t)bb * LP + NN + r / DM) * DM + (r % DM)] = 0.0f;
    }

    __shared__ float sE[11][DM];     // rows t0 .. t0+10 (22.5 KB)
    int t0 = blockIdx.x * 8;
    int b = blockIdx.y;
    int tid = threadIdx.x;

    for (int v = tid; v < 11 * 128; v += 128) {
        int r = v >> 7;
        int c4 = (v & 127) * 4;
        int t = t0 + r;
        float4 e = {0.f, 0.f, 0.f, 0.f};
        if (t < NN) {
            int id = x[b * NN + t];
            e = *(const float4*)(emb + (size_t)id * DM + c4);
        }
        *(float4*)(&sE[r][c4]) = e;
    }
    __syncthreads();

    int d0 = tid * 4;
    float w[4][4];
#pragma unroll
    for (int j = 0; j < 4; j++) {
        float4 wv = *(const float4*)(dww + (d0 + j) * 4);
        w[j][0] = wv.x; w[j][1] = wv.y; w[j][2] = wv.z; w[j][3] = wv.w;
    }
    float4 bb = *(const float4*)(dwb + d0);

#pragma unroll
    for (int tok = 0; tok < 8; tok++) {
        float acc[4] = {bb.x, bb.y, bb.z, bb.w};
#pragma unroll
        for (int k = 0; k < 4; k++) {
            float4 e = *(const float4*)(&sE[tok + k][d0]);
            acc[0] += e.x * w[0][k];
            acc[1] += e.y * w[1][k];
            acc[2] += e.z * w[2][k];
            acc[3] += e.w * w[3][k];
        }
        size_t base = ((size_t)(b * NN + t0 + tok)) * DM + d0;
        __nv_bfloat16 h[4], l[4];
#pragma unroll
        for (int j = 0; j < 4; j++) {
            h[j] = __float2bfloat16(acc[j]);
            l[j] = __float2bfloat16(acc[j] - __bfloat162float(h[j]));
        }
        __nv_bfloat162* ph = (__nv_bfloat162*)(g_Yh + base);
        __nv_bfloat162* pl = (__nv_bfloat162*)(g_Yl + base);
        ph[0] = __halves2bfloat162(h[0], h[1]);
        ph[1] = __halves2bfloat162(h[2], h[3]);
        pl[0] = __halves2bfloat162(l[0], l[1]);
        pl[1] = __halves2bfloat162(l[2], l[3]);
    }
}

// ---------------- HMMA GEMM: persistent CTAs, bf16x3, cp.async 3-stage ----------------
#define TILE_B 8192          // 128 rows * 64 B
#define STAGE_B (4*TILE_B)   // Ah, Al, Bh, Bl = 32768
#define GEMM_SMEM (3*STAGE_B)  // 98304

__device__ __forceinline__ uint32_t swz(uint32_t row, uint32_t chunk) {
    return row * 64 + ((chunk ^ ((row >> 1) & 3)) << 4);
}
__device__ __forceinline__ void ldsm4(uint32_t* r, uint32_t addr) {
    asm volatile("ldmatrix.sync.aligned.m8n8.x4.shared.b16 {%0,%1,%2,%3}, [%4];"
                 : "=r"(r[0]), "=r"(r[1]), "=r"(r[2]), "=r"(r[3]) : "r"(addr));
}
__device__ __forceinline__ void mma16816(float* c, const uint32_t* a, const uint32_t* b) {
    asm volatile(
        "mma.sync.aligned.m16n8k16.row.col.f32.bf16.bf16.f32 "
        "{%0,%1,%2,%3}, {%4,%5,%6,%7}, {%8,%9}, {%0,%1,%2,%3};"
        : "+f"(c[0]), "+f"(c[1]), "+f"(c[2]), "+f"(c[3])
        : "r"(a[0]), "r"(a[1]), "r"(a[2]), "r"(a[3]), "r"(b[0]), "r"(b[1]));
}
__device__ __forceinline__ void cpa16(uint32_t dst, const void* src) {
    asm volatile("cp.async.cg.shared.global [%0], [%1], 16;" :: "r"(dst), "l"(src));
}

__global__ void __launch_bounds__(256, 2) k_gemm_mma(const float* __restrict__ bias,
                                                     const float* __restrict__ sw) {
    extern __shared__ char sm[];
    uint32_t smu = (uint32_t)__cvta_generic_to_shared(sm);

    int tid = threadIdx.x, wid = tid >> 5, lane = tid & 31;
    int warp_m = wid & 1;
    int warp_n = wid >> 1;

    int r0 = tid >> 2, cc0 = tid & 3;
    int r1 = r0 + 64;
    uint32_t so0 = swz(r0, cc0);
    uint32_t so1 = swz(r1, cc0);

    int lr = lane & 7, g = lane >> 3;
    int a_row = (g & 1) * 8 + lr;
    int a_kc8 = (g >> 1);
    int b_nrw = (g >> 1) * 8 + lr;
    int b_kc8 = (g & 1);

    auto load_stage_for = [&](int tile, int kc, int stage) {
        int mtile = tile & 127;
        int bn = tile >> 7;
        const __nv_bfloat16* gAh = g_Yh + (size_t)mtile * 128 * DM;
        const __nv_bfloat16* gAl = g_Yl + (size_t)mtile * 128 * DM;
        const __nv_bfloat16* gBh = g_Wh + (size_t)bn * 128 * DM;
        const __nv_bfloat16* gBl = g_Wl + (size_t)bn * 128 * DM;
        uint32_t base = smu + stage * STAGE_B;
        size_t go0 = (size_t)r0 * DM + kc * 32 + cc0 * 8;
        size_t go1 = (size_t)r1 * DM + kc * 32 + cc0 * 8;
        cpa16(base + so0, gAh + go0);
        cpa16(base + so1, gAh + go1);
        cpa16(base + TILE_B + so0, gAl + go0);
        cpa16(base + TILE_B + so1, gAl + go1);
        cpa16(base + 2 * TILE_B + so0, gBh + go0);
        cpa16(base + 2 * TILE_B + so1, gBh + go1);
        cpa16(base + 3 * TILE_B + so0, gBl + go0);
        cpa16(base + 3 * TILE_B + so1, gBl + go1);
        asm volatile("cp.async.commit_group;");
    };

    int tile0 = blockIdx.x;
    load_stage_for(tile0, 0, 0);
    load_stage_for(tile0, 1, 1);

    for (int tile = tile0; tile < GEMM_TILES; tile += GEMM_GRID) {
        int mtile = tile & 127;
        int bn = tile >> 7;

        float c[4][4][4];
#pragma unroll
        for (int mt = 0; mt < 4; mt++)
#pragma unroll
            for (int nt = 0; nt < 4; nt++)
#pragma unroll
                for (int e = 0; e < 4; e++) c[mt][nt][e] = 0.0f;

        for (int kc = 0; kc < 16; kc++) {
            if (kc + 1 < 16) asm volatile("cp.async.wait_group 1;");
            else             asm volatile("cp.async.wait_group 0;");
            __syncthreads();
            if (kc + 2 < 16) load_stage_for(tile, kc + 2, (kc + 2) % 3);

            uint32_t sAh = smu + (kc % 3) * STAGE_B;
            uint32_t sAl = sAh + TILE_B;
            uint32_t sBh = sAh + 2 * TILE_B;
            uint32_t sBl = sAh + 3 * TILE_B;

#pragma unroll
            for (int ks = 0; ks < 2; ks++) {
                uint32_t bh[8], bl[8], a[4][4];
#pragma unroll
                for (int hh = 0; hh < 2; hh++) {
                    uint32_t row = warp_n * 32 + hh * 16 + b_nrw;
                    uint32_t off = swz(row, 2 * ks + b_kc8);
                    ldsm4(bh + hh * 4, sBh + off);
                    ldsm4(bl + hh * 4, sBl + off);
                }
#pragma unroll
                for (int mt = 0; mt < 4; mt++) {
                    uint32_t row = warp_m * 64 + mt * 16 + a_row;
                    uint32_t off = swz(row, 2 * ks + a_kc8);
                    ldsm4(a[mt], sAh + off);
                }
#pragma unroll
                for (int mt = 0; mt < 4; mt++)
#pragma unroll
                    for (int nt = 0; nt < 4; nt++) {
                        int bi = (nt >> 1) * 4 + (nt & 1) * 2;
                        uint32_t b0[2] = {bh[bi], bh[bi + 1]};
                        mma16816(c[mt][nt], a[mt], b0);
                        uint32_t b1[2] = {bl[bi], bl[bi + 1]};
                        mma16816(c[mt][nt], a[mt], b1);
                    }
#pragma unroll
                for (int mt = 0; mt < 4; mt++) {
                    uint32_t row = warp_m * 64 + mt * 16 + a_row;
                    uint32_t off = swz(row, 2 * ks + a_kc8);
                    ldsm4(a[mt], sAl + off);
                }
#pragma unroll
                for (int mt = 0; mt < 4; mt++)
#pragma unroll
                    for (int nt = 0; nt < 4; nt++) {
                        int bi = (nt >> 1) * 4 + (nt & 1) * 2;
                        uint32_t b0[2] = {bh[bi], bh[bi + 1]};
                        mma16816(c[mt][nt], a[mt], b0);
                    }
            }
        }

        // prefetch next tile's first two stages before the (register-only) epilogue
        int ntile = tile + GEMM_GRID;
        if (ntile < GEMM_TILES) {
            __syncthreads();   // all warps done reading stage smem
            load_stage_for(ntile, 0, 0);
            load_stage_for(ntile, 1, 1);
        }

        // epilogue: bias add + fused tdot + store
        float tp[4][2];
#pragma unroll
        for (int mt = 0; mt < 4; mt++) { tp[mt][0] = 0.0f; tp[mt][1] = 0.0f; }

#pragma unroll
        for (int mt = 0; mt < 4; mt++) {
            int row0 = mtile * 128 + warp_m * 64 + mt * 16 + (lane >> 2);
            int row1 = row0 + 8;
            int b0i = row0 >> 12, l0i = row0 & 4095;
            int b1i = row1 >> 12, l1i = row1 & 4095;
            float* o0 = g_Y2 + ((size_t)b0i * LP + l0i) * DM;
            float* o1 = g_Y2 + ((size_t)b1i * LP + l1i) * DM;
#pragma unroll
            for (int nt = 0; nt < 4; nt++) {
                int col = bn * 128 + warp_n * 32 + nt * 8 + 2 * (lane & 3);
                float bi0 = bias[col], bi1 = bias[col + 1];
                float s0 = sw[col], s1 = sw[col + 1];
                float v00 = c[mt][nt][0] + bi0, v01 = c[mt][nt][1] + bi1;
                float v10 = c[mt][nt][2] + bi0, v11 = c[mt][nt][3] + bi1;
                tp[mt][0] += v00 * s0 + v01 * s1;
                tp[mt][1] += v10 * s0 + v11 * s1;
                float2 w0 = {v00, v01}, w1 = {v10, v11};
                *(float2*)(o0 + col) = w0;
                *(float2*)(o1 + col) = w1;
            }
        }
#pragma unroll
        for (int mt = 0; mt < 4; mt++) {
#pragma unroll
            for (int rs = 0; rs < 2; rs++) {
                float r = tp[mt][rs];
                r += __shfl_xor_sync(0xffffffff, r, 1);
                r += __shfl_xor_sync(0xffffffff, r, 2);
                if ((lane & 3) == 0) {
                    int row = mtile * 128 + warp_m * 64 + mt * 16 + rs * 8 + (lane >> 2);
                    int bb = row >> 12, ll = row & 4095;
                    atomicAdd(&g_T[bb * LP + ll], r);
                }
            }
        }
    }
}

// ---------------- block means of T + softmax over k ----------------
__global__ void __launch_bounds__(256) k_scores(const float* __restrict__ sb) {
    int idx = blockIdx.x * blockDim.x + threadIdx.x;
    if (idx >= NROWS) return;
    int b = idx / LP, l = idx % LP;
    const float* Tb = g_T + (size_t)b * LP;
    float v[4];
    v[0] = Tb[l];
    { int j = l & ~1;      v[1] = (Tb[j] + Tb[j + 1]) * 0.5f; }
    { int j = (l / 3) * 3; v[2] = (Tb[j] + Tb[j + 1] + Tb[j + 2]) * (1.0f / 3.0f); }
    { int j = l & ~3;      v[3] = (Tb[j] + Tb[j + 1] + Tb[j + 2] + Tb[j + 3]) * 0.25f; }
    float mx = v[0];
#pragma unroll
    for (int k = 1; k < 4; k++) mx = fmaxf(mx, v[k]);
    float e[4], z = 0.0f;
#pragma unroll
    for (int k = 0; k < 4; k++) { e[k] = __expf(v[k] - mx); z += e[k]; }
    float inv = 1.0f / z;
    float4 o = {e[0] * inv, e[1] * inv, e[2] * inv, e[3] * inv};
    *(float4*)(g_S + (size_t)idx * 4) = o;
}

// ---------------- score attention, 24-way key split, 2 queries/thread, f32x2 ----------------
// z is NOT accumulated: keys are softmaxed (components sum to 1), so
// z = sum of the 4 components of the numerator.
__global__ void __launch_bounds__(128) k_attn_part() {
    __shared__ float4 sS[LQS];   // 171 keys = 2.7 KB
    int b = blockIdx.y, sp = blockIdx.z;
    const float4* Sb = (const float4*)(g_S + ((size_t)b * LP + sp * LQS) * 4);
    for (int j = threadIdx.x; j < LQS; j += 128) sS[j] = Sb[j];
    __syncthreads();

    int i0 = blockIdx.x * 128 + threadIdx.x;
    if (i0 >= HQ) return;
    int i1 = i0 + HQ;

    const float L2E = 1.4426950408889634f;
    float4 q0 = *(const float4*)(g_S + ((size_t)b * LP + i0) * 4);
    float4 q1 = *(const float4*)(g_S + ((size_t)b * LP + i1) * 4);
    unsigned long long q0a = pack2(q0.x * L2E, q0.y * L2E);
    unsigned long long q0b = pack2(q0.z * L2E, q0.w * L2E);
    unsigned long long q1a = pack2(q1.x * L2E, q1.y * L2E);
    unsigned long long q1b = pack2(q1.z * L2E, q1.w * L2E);

    unsigned long long A0a = 0, A0b = 0, A1a = 0, A1b = 0;

    const ulonglong2* sSv = (const ulonglong2*)sS;
#pragma unroll 3
    for (int j = 0; j < LQS; j++) {
        ulonglong2 sv = sSv[j];
        unsigned long long d0p = fma2(q0b, sv.y, mul2(q0a, sv.x));
        float d0l, d0h; unpack2(d0p, d0l, d0h);
        float e0;
        asm("ex2.approx.f32 %0, %1;" : "=f"(e0) : "f"(d0l + d0h));
        unsigned long long e0p = pack2(e0, e0);
        A0a = fma2(e0p, sv.x, A0a);
        A0b = fma2(e0p, sv.y, A0b);
        unsigned long long d1p = fma2(q1b, sv.y, mul2(q1a, sv.x));
        float d1l, d1h; unpack2(d1p, d1l, d1h);
        float e1;
        asm("ex2.approx.f32 %0, %1;" : "=f"(e1) : "f"(d1l + d1h));
        unsigned long long e1p = pack2(e1, e1);
        A1a = fma2(e1p, sv.x, A1a);
        A1b = fma2(e1p, sv.y, A1b);
    }

    float4 r0, r1;
    unpack2(A0a, r0.x, r0.y); unpack2(A0b, r0.z, r0.w);
    unpack2(A1a, r1.x, r1.y); unpack2(A1b, r1.z, r1.w);
    int row0 = b * LP + i0, row1 = b * LP + i1;
    g_Pa[sp][row0] = r0;
    g_Pa[sp][row1] = r1;
}

// ---------------- output: split-reduce + one-thread weight build + pooled store ----------
__global__ void __launch_bounds__(128) k_out(float* __restrict__ out) {
    __shared__ float4 s2s[4];
    __shared__ float ws[8];
    int g = blockIdx.x;
    int b = blockIdx.y;
    int base = 4 * g - 2;
    int tid = threadIdx.x;

    if (tid < 4) {
        int row = b * LP + 4 * g + tid;
        float4 a = make_float4(0.0f, 0.0f, 0.0f, 0.0f);
#pragma unroll
        for (int s = 0; s < NSPLIT; s++) {
            float4 p = g_Pa[s][row];
            a.x += p.x; a.y += p.y; a.z += p.z; a.w += p.w;
        }
        float z = a.x + a.y + a.z + a.w;   // keys sum to 1 -> denominator
        float inv = 1.0f / z;
        s2s[tid] = make_float4(a.x * inv, a.y * inv, a.z * inv, a.w * inv);
    }
    __syncthreads();

    if (tid == 0) {
        float w[8];
#pragma unroll
        for (int r = 0; r < 8; r++) w[r] = 0.0f;
#pragma unroll
        for (int lo = 0; lo < 4; lo++) {
            int l = 4 * g + lo;
            float4 s2 = s2s[lo];
            w[l - base] += s2.x * 0.25f;
            { int j0 = l & ~1;      float c = s2.y * (0.25f * 0.5f);
              w[j0 - base] += c; w[j0 + 1 - base] += c; }
            { int j0 = (l / 3) * 3; float c = s2.z * (0.25f / 3.0f);
              w[j0 - base] += c; w[j0 + 1 - base] += c; w[j0 + 2 - base] += c; }
            { int j0 = l & ~3;      float c = s2.w * (0.25f * 0.25f);
              w[j0 - base] += c; w[j0 + 1 - base] += c;
              w[j0 + 2 - base] += c; w[j0 + 3 - base] += c; }
        }
#pragma unroll
        for (int r = 0; r < 8; r++) ws[r] = w[r];
    }
    __syncthreads();

    int d = tid * 4;
    const float* Yb = g_Y2 + ((size_t)b * LP + base) * DM + d;
    float4 acc = {0.0f, 0.0f, 0.0f, 0.0f};
#pragma unroll
    for (int r = 0; r < 8; r++) {
        int row = base + r;
        float wr = ws[r];
        if (row >= 0 && wr != 0.0f) {
            float4 v = *(const float4*)(Yb + (size_t)r * DM);
            acc.x += wr * v.x; acc.y += wr * v.y;
            acc.z += wr * v.z; acc.w += wr * v.w;
        }
    }
    *(float4*)(out + ((size_t)(b * 1024 + g)) * DM + d) = acc;
}

// ---------------- launcher ----------------
extern "C" void kernel_launch(void* const* d_in, const int* in_sizes, int n_in,
                              void* d_out, int out_size) {
    const int*   x   = (const int*)  d_in[0];
    const float* emb = (const float*)d_in[1];
    const float* dww = (const float*)d_in[2];
    const float* dwb = (const float*)d_in[3];
    const float* pww = (const float*)d_in[4];
    const float* pwb = (const float*)d_in[5];
    const float* sw  = (const float*)d_in[6];
    const float* sb  = (const float*)d_in[7];
    float* out = (float*)d_out;

    cudaFuncSetAttribute(k_gemm_mma, cudaFuncAttributeMaxDynamicSharedMemorySize, GEMM_SMEM);

    k_conv<<<dim3(NN / 8, BQ), 128>>>(x, emb, dww, dwb, pww);
    k_gemm_mma<<<GEMM_GRID, 256, GEMM_SMEM>>>(pwb, sw);
    k_scores<<<(NROWS + 255) / 256, 256>>>(sb);
    k_attn_part<<<dim3((HQ + 127) / 128, BQ, NSPLIT), 128>>>();
    k_out<<<dim3(1024, BQ), 128>>>(out);
}

// round 15
// speedup vs baseline: 1.1126x; 1.1126x over previous
#include <cuda_runtime.h>
#include <cuda_bf16.h>
#include <cstdint>

#define BQ 4
#define NN 4096
#define DM 512
#define LP 4104   // ceil(4096/12)*12
#define NROWS (BQ*LP)
#define NMON 330          // monomials of total degree <= 7 in 4 vars
#define MCH 108           // keys per moments chunk
#define NCHK 38           // 38*108 = 4104

// ---------------- scratch (device globals) ----------------
__device__ __nv_bfloat16 g_Yh[(size_t)BQ*NN*DM];   // conv output hi
__device__ __nv_bfloat16 g_Yl[(size_t)BQ*NN*DM];   // conv output lo
__device__ __nv_bfloat16 g_Wh[DM*DM];              // pw_w hi
__device__ __nv_bfloat16 g_Wl[DM*DM];              // pw_w lo
__device__ float g_Y2[(size_t)BQ*LP*DM];           // pointwise output
__device__ float g_T [NROWS];                      // per-position score dot (atomic)
__device__ float g_S [NROWS*4];                    // softmaxed block scores
__device__ float g_S2[NROWS*4];                    // attention-mixed scores
__device__ float g_M [BQ][NMON*4];                 // Taylor moments (atomic)
__device__ uchar4 g_MON[NMON];                     // monomial exponents
__device__ float  g_CINV[NMON];                    // 1/prod(a_i!)

// ---------------- conv (+ fused prep: W split, T zero, Y2 pad zero, monomial tables) ----
__global__ void __launch_bounds__(128) k_conv(const int* __restrict__ x,
                                              const float* __restrict__ emb,
                                              const float* __restrict__ dww,
                                              const float* __restrict__ dwb,
                                              const float* __restrict__ W) {
    // fused prep: 2048 blocks * 128 threads = 262144 = DM*DM exactly
    int gidx = (blockIdx.y * gridDim.x + blockIdx.x) * 128 + threadIdx.x;
    {
        float w = W[gidx];
        __nv_bfloat16 h = __float2bfloat16(w);
        g_Wh[gidx] = h;
        g_Wl[gidx] = __float2bfloat16(w - __bfloat162float(h));
    }
    if (gidx < NROWS) g_T[gidx] = 0.0f;
    if (gidx < BQ * 8 * DM) {
        int bb = gidx / (8 * DM);
        int r = gidx % (8 * DM);
        g_Y2[((size_t)bb * LP + NN + r / DM) * DM + (r % DM)] = 0.0f;
    }
    if (gidx < BQ * NMON * 4) ((float*)g_M)[gidx] = 0.0f;
    if (gidx < 4096) {   // enumerate monomials: a_i in 0..7, total <= 7
        int a1 = (gidx >> 9) & 7, a2 = (gidx >> 6) & 7;
        int a3 = (gidx >> 3) & 7, a4 = gidx & 7;
        if (a1 + a2 + a3 + a4 <= 7) {
            int r = 0;
            for (int b1 = 0; b1 < a1; b1++) { int m = 7 - b1; r += (m+1)*(m+2)*(m+3)/6; }
            for (int b2 = 0; b2 < a2; b2++) { int m = 7 - a1 - b2; r += (m+1)*(m+2)/2; }
            for (int b3 = 0; b3 < a3; b3++) { int m = 7 - a1 - a2 - b3; r += m + 1; }
            r += a4;
            g_MON[r] = make_uchar4(a1, a2, a3, a4);
            int f1 = 1, f2 = 1, f3 = 1, f4 = 1;
            for (int k = 2; k <= a1; k++) f1 *= k;
            for (int k = 2; k <= a2; k++) f2 *= k;
            for (int k = 2; k <= a3; k++) f3 *= k;
            for (int k = 2; k <= a4; k++) f4 *= k;
            g_CINV[r] = 1.0f / (float)(f1 * f2 * f3 * f4);
        }
    }

    __shared__ float sE[11][DM];     // rows t0 .. t0+10 (22.5 KB)
    int t0 = blockIdx.x * 8;
    int b = blockIdx.y;
    int tid = threadIdx.x;

    for (int v = tid; v < 11 * 128; v += 128) {
        int r = v >> 7;
        int c4 = (v & 127) * 4;
        int t = t0 + r;
        float4 e = {0.f, 0.f, 0.f, 0.f};
        if (t < NN) {
            int id = x[b * NN + t];
            e = *(const float4*)(emb + (size_t)id * DM + c4);
        }
        *(float4*)(&sE[r][c4]) = e;
    }
    __syncthreads();

    int d0 = tid * 4;
    float w[4][4];
#pragma unroll
    for (int j = 0; j < 4; j++) {
        float4 wv = *(const float4*)(dww + (d0 + j) * 4);
        w[j][0] = wv.x; w[j][1] = wv.y; w[j][2] = wv.z; w[j][3] = wv.w;
    }
    float4 bb = *(const float4*)(dwb + d0);

#pragma unroll
    for (int tok = 0; tok < 8; tok++) {
        float acc[4] = {bb.x, bb.y, bb.z, bb.w};
#pragma unroll
        for (int k = 0; k < 4; k++) {
            float4 e = *(const float4*)(&sE[tok + k][d0]);
            acc[0] += e.x * w[0][k];
            acc[1] += e.y * w[1][k];
            acc[2] += e.z * w[2][k];
            acc[3] += e.w * w[3][k];
        }
        size_t base = ((size_t)(b * NN + t0 + tok)) * DM + d0;
        __nv_bfloat16 h[4], l[4];
#pragma unroll
        for (int j = 0; j < 4; j++) {
            h[j] = __float2bfloat16(acc[j]);
            l[j] = __float2bfloat16(acc[j] - __bfloat162float(h[j]));
        }
        __nv_bfloat162* ph = (__nv_bfloat162*)(g_Yh + base);
        __nv_bfloat162* pl = (__nv_bfloat162*)(g_Yl + base);
        ph[0] = __halves2bfloat162(h[0], h[1]);
        ph[1] = __halves2bfloat162(h[2], h[3]);
        pl[0] = __halves2bfloat162(l[0], l[1]);
        pl[1] = __halves2bfloat162(l[2], l[3]);
    }
}

// ---------------- HMMA GEMM: Y2 = Y @ W^T + bias, bf16x3, cp.async 3-stage ----------------
#define TILE_B 8192          // 128 rows * 64 B
#define STAGE_B (4*TILE_B)   // Ah, Al, Bh, Bl = 32768
#define GEMM_SMEM (3*STAGE_B)  // 98304

__device__ __forceinline__ uint32_t swz(uint32_t row, uint32_t chunk) {
    return row * 64 + ((chunk ^ ((row >> 1) & 3)) << 4);
}
__device__ __forceinline__ void ldsm4(uint32_t* r, uint32_t addr) {
    asm volatile("ldmatrix.sync.aligned.m8n8.x4.shared.b16 {%0,%1,%2,%3}, [%4];"
                 : "=r"(r[0]), "=r"(r[1]), "=r"(r[2]), "=r"(r[3]) : "r"(addr));
}
__device__ __forceinline__ void mma16816(float* c, const uint32_t* a, const uint32_t* b) {
    asm volatile(
        "mma.sync.aligned.m16n8k16.row.col.f32.bf16.bf16.f32 "
        "{%0,%1,%2,%3}, {%4,%5,%6,%7}, {%8,%9}, {%0,%1,%2,%3};"
        : "+f"(c[0]), "+f"(c[1]), "+f"(c[2]), "+f"(c[3])
        : "r"(a[0]), "r"(a[1]), "r"(a[2]), "r"(a[3]), "r"(b[0]), "r"(b[1]));
}
__device__ __forceinline__ void cpa16(uint32_t dst, const void* src) {
    asm volatile("cp.async.cg.shared.global [%0], [%1], 16;" :: "r"(dst), "l"(src));
}

__global__ void __launch_bounds__(256, 2) k_gemm_mma(const float* __restrict__ bias,
                                                     const float* __restrict__ sw) {
    extern __shared__ char sm[];
    uint32_t smu = (uint32_t)__cvta_generic_to_shared(sm);

    int tid = threadIdx.x, wid = tid >> 5, lane = tid & 31;
    int warp_m = wid & 1;
    int warp_n = wid >> 1;
    int mtile = blockIdx.x;
    int bn = blockIdx.y;

    const __nv_bfloat16* gA[2] = {g_Yh + (size_t)mtile * 128 * DM,
                                  g_Yl + (size_t)mtile * 128 * DM};
    const __nv_bfloat16* gB[2] = {g_Wh + (size_t)bn * 128 * DM,
                                  g_Wl + (size_t)bn * 128 * DM};

    int r0 = tid >> 2, cc0 = tid & 3;
    int r1 = r0 + 64;
    uint32_t so0 = swz(r0, cc0);
    uint32_t so1 = swz(r1, cc0);

    auto load_stage = [&](int kc, int stage) {
        uint32_t base = smu + stage * STAGE_B;
        size_t go0 = (size_t)r0 * DM + kc * 32 + cc0 * 8;
        size_t go1 = (size_t)r1 * DM + kc * 32 + cc0 * 8;
#pragma unroll
        for (int p = 0; p < 2; p++) {
            cpa16(base + p * TILE_B + so0, gA[p] + go0);
            cpa16(base + p * TILE_B + so1, gA[p] + go1);
            cpa16(base + (2 + p) * TILE_B + so0, gB[p] + go0);
            cpa16(base + (2 + p) * TILE_B + so1, gB[p] + go1);
        }
        asm volatile("cp.async.commit_group;");
    };

    float c[4][4][4];
#pragma unroll
    for (int mt = 0; mt < 4; mt++)
#pragma unroll
        for (int nt = 0; nt < 4; nt++)
#pragma unroll
            for (int e = 0; e < 4; e++) c[mt][nt][e] = 0.0f;

    int lr = lane & 7, g = lane >> 3;
    int a_row = (g & 1) * 8 + lr;
    int a_kc8 = (g >> 1);
    int b_nrw = (g >> 1) * 8 + lr;
    int b_kc8 = (g & 1);

    load_stage(0, 0);
    load_stage(1, 1);

    for (int kc = 0; kc < 16; kc++) {
        if (kc + 1 < 16) asm volatile("cp.async.wait_group 1;");
        else             asm volatile("cp.async.wait_group 0;");
        __syncthreads();
        if (kc + 2 < 16) load_stage(kc + 2, (kc + 2) % 3);

        uint32_t sAh = smu + (kc % 3) * STAGE_B;
        uint32_t sAl = sAh + TILE_B;
        uint32_t sBh = sAh + 2 * TILE_B;
        uint32_t sBl = sAh + 3 * TILE_B;

#pragma unroll
        for (int ks = 0; ks < 2; ks++) {
            uint32_t bh[8], bl[8], a[4][4];
#pragma unroll
            for (int hh = 0; hh < 2; hh++) {
                uint32_t row = warp_n * 32 + hh * 16 + b_nrw;
                uint32_t off = swz(row, 2 * ks + b_kc8);
                ldsm4(bh + hh * 4, sBh + off);
                ldsm4(bl + hh * 4, sBl + off);
            }
#pragma unroll
            for (int mt = 0; mt < 4; mt++) {
                uint32_t row = warp_m * 64 + mt * 16 + a_row;
                uint32_t off = swz(row, 2 * ks + a_kc8);
                ldsm4(a[mt], sAh + off);
            }
#pragma unroll
            for (int mt = 0; mt < 4; mt++)
#pragma unroll
                for (int nt = 0; nt < 4; nt++) {
                    int bi = (nt >> 1) * 4 + (nt & 1) * 2;
                    uint32_t b0[2] = {bh[bi], bh[bi + 1]};
                    mma16816(c[mt][nt], a[mt], b0);
                    uint32_t b1[2] = {bl[bi], bl[bi + 1]};
                    mma16816(c[mt][nt], a[mt], b1);
                }
#pragma unroll
            for (int mt = 0; mt < 4; mt++) {
                uint32_t row = warp_m * 64 + mt * 16 + a_row;
                uint32_t off = swz(row, 2 * ks + a_kc8);
                ldsm4(a[mt], sAl + off);
            }
#pragma unroll
            for (int mt = 0; mt < 4; mt++)
#pragma unroll
                for (int nt = 0; nt < 4; nt++) {
                    int bi = (nt >> 1) * 4 + (nt & 1) * 2;
                    uint32_t b0[2] = {bh[bi], bh[bi + 1]};
                    mma16816(c[mt][nt], a[mt], b0);
                }
        }
    }

    float tp[4][2];
#pragma unroll
    for (int mt = 0; mt < 4; mt++) { tp[mt][0] = 0.0f; tp[mt][1] = 0.0f; }

#pragma unroll
    for (int mt = 0; mt < 4; mt++) {
        int row0 = mtile * 128 + warp_m * 64 + mt * 16 + (lane >> 2);
        int row1 = row0 + 8;
        int b0i = row0 >> 12, l0i = row0 & 4095;
        int b1i = row1 >> 12, l1i = row1 & 4095;
        float* o0 = g_Y2 + ((size_t)b0i * LP + l0i) * DM;
        float* o1 = g_Y2 + ((size_t)b1i * LP + l1i) * DM;
#pragma unroll
        for (int nt = 0; nt < 4; nt++) {
            int col = bn * 128 + warp_n * 32 + nt * 8 + 2 * (lane & 3);
            float bi0 = bias[col], bi1 = bias[col + 1];
            float s0 = sw[col], s1 = sw[col + 1];
            float v00 = c[mt][nt][0] + bi0, v01 = c[mt][nt][1] + bi1;
            float v10 = c[mt][nt][2] + bi0, v11 = c[mt][nt][3] + bi1;
            tp[mt][0] += v00 * s0 + v01 * s1;
            tp[mt][1] += v10 * s0 + v11 * s1;
            float2 w0 = {v00, v01}, w1 = {v10, v11};
            *(float2*)(o0 + col) = w0;
            *(float2*)(o1 + col) = w1;
        }
    }
#pragma unroll
    for (int mt = 0; mt < 4; mt++) {
#pragma unroll
        for (int rs = 0; rs < 2; rs++) {
            float r = tp[mt][rs];
            r += __shfl_xor_sync(0xffffffff, r, 1);
            r += __shfl_xor_sync(0xffffffff, r, 2);
            if ((lane & 3) == 0) {
                int row = mtile * 128 + warp_m * 64 + mt * 16 + rs * 8 + (lane >> 2);
                int bb = row >> 12, ll = row & 4095;
                atomicAdd(&g_T[bb * LP + ll], r);
            }
        }
    }
}

// ---------------- block means of T + softmax over k ----------------
__global__ void __launch_bounds__(256) k_scores(const float* __restrict__ sb) {
    int idx = blockIdx.x * blockDim.x + threadIdx.x;
    if (idx >= NROWS) return;
    int b = idx / LP, l = idx % LP;
    const float* Tb = g_T + (size_t)b * LP;
    float v[4];
    v[0] = Tb[l];
    { int j = l & ~1;      v[1] = (Tb[j] + Tb[j + 1]) * 0.5f; }
    { int j = (l / 3) * 3; v[2] = (Tb[j] + Tb[j + 1] + Tb[j + 2]) * (1.0f / 3.0f); }
    { int j = l & ~3;      v[3] = (Tb[j] + Tb[j + 1] + Tb[j + 2] + Tb[j + 3]) * 0.25f; }
    float mx = v[0];
#pragma unroll
    for (int k = 1; k < 4; k++) mx = fmaxf(mx, v[k]);
    float e[4], z = 0.0f;
#pragma unroll
    for (int k = 0; k < 4; k++) { e[k] = __expf(v[k] - mx); z += e[k]; }
    float inv = 1.0f / z;
    float4 o = {e[0] * inv, e[1] * inv, e[2] * inv, e[3] * inv};
    *(float4*)(g_S + (size_t)idx * 4) = o;
}

// ---------------- Taylor moments: M[a][i] = sum_j s_j^a * s_ji, coeff folded ----------
__global__ void __launch_bounds__(384) k_moments() {
    __shared__ float sPow[4 * 8 * MCH];   // (i*8+e)*MCH + j
    int b = blockIdx.y, ch = blockIdx.x;
    int tid = threadIdx.x;

    if (tid < MCH) {
        float4 s = *(const float4*)(g_S + ((size_t)b * LP + ch * MCH + tid) * 4);
        float comp[4] = {s.x, s.y, s.z, s.w};
#pragma unroll
        for (int i = 0; i < 4; i++) {
            float p = 1.0f;
#pragma unroll
            for (int e = 0; e < 8; e++) {
                sPow[(i * 8 + e) * MCH + tid] = p;
                p *= comp[i];
            }
        }
    }
    __syncthreads();

    if (tid < NMON) {
        uchar4 a = g_MON[tid];
        float c = g_CINV[tid];
        const float* p0 = sPow + (0 * 8 + a.x) * MCH;
        const float* p1 = sPow + (1 * 8 + a.y) * MCH;
        const float* p2 = sPow + (2 * 8 + a.z) * MCH;
        const float* p3 = sPow + (3 * 8 + a.w) * MCH;
        const float* s0 = sPow + 1 * MCH;            // s_x
        const float* s1 = sPow + 9 * MCH;            // s_y
        const float* s2 = sPow + 17 * MCH;           // s_z
        const float* s3 = sPow + 25 * MCH;           // s_w
        float acc0 = 0.f, acc1 = 0.f, acc2 = 0.f, acc3 = 0.f;
#pragma unroll 4
        for (int j = 0; j < MCH; j++) {
            float v = p0[j] * p1[j] * p2[j] * p3[j];
            acc0 += v * s0[j];
            acc1 += v * s1[j];
            acc2 += v * s2[j];
            acc3 += v * s3[j];
        }
        atomicAdd(&g_M[b][tid * 4 + 0], acc0 * c);
        atomicAdd(&g_M[b][tid * 4 + 1], acc1 * c);
        atomicAdd(&g_M[b][tid * 4 + 2], acc2 * c);
        atomicAdd(&g_M[b][tid * 4 + 3], acc3 * c);
    }
}

// ---------------- eval: S2(q) = N/z, N_i = sum_a q^a M'[a][i], z = sum_i N_i ----------
__global__ void __launch_bounds__(128) k_eval() {
    __shared__ float sM[NMON * 4];
    __shared__ uchar4 sMON[NMON];
    __shared__ float qp[128 * 33];   // per-thread 32 powers, stride 33 (conflict-free)
    int b = blockIdx.y;
    int tid = threadIdx.x;
    int i0 = blockIdx.x * 128 + tid;

    for (int t = tid; t < NMON * 4; t += 128) sM[t] = g_M[b][t];
    for (int t = tid; t < NMON; t += 128) sMON[t] = g_MON[t];

    float4 q = {0.f, 0.f, 0.f, 0.f};
    if (i0 < LP) q = *(const float4*)(g_S + ((size_t)b * LP + i0) * 4);
    {
        float comp[4] = {q.x, q.y, q.z, q.w};
        int base = tid * 33;
#pragma unroll
        for (int i = 0; i < 4; i++) {
            float p = 1.0f;
#pragma unroll
            for (int e = 0; e < 8; e++) {
                qp[base + i * 8 + e] = p;
                p *= comp[i];
            }
        }
    }
    __syncthreads();

    int base = tid * 33;
    float a0 = 0.f, a1 = 0.f, a2 = 0.f, a3 = 0.f;
#pragma unroll 2
    for (int m = 0; m < NMON; m++) {
        uchar4 a = sMON[m];
        float v = qp[base + a.x] * qp[base + 8 + a.y]
                * qp[base + 16 + a.z] * qp[base + 24 + a.w];
        float4 Mv = *(const float4*)(&sM[m * 4]);
        a0 = fmaf(v, Mv.x, a0);
        a1 = fmaf(v, Mv.y, a1);
        a2 = fmaf(v, Mv.z, a2);
        a3 = fmaf(v, Mv.w, a3);
    }
    if (i0 < LP) {
        float inv = 1.0f / (a0 + a1 + a2 + a3);
        float4 r = {a0 * inv, a1 * inv, a2 * inv, a3 * inv};
        *(float4*)(g_S2 + ((size_t)b * LP + i0) * 4) = r;
    }
}

// ---------------- output: one-thread weight build + pooled store ----------
__global__ void __launch_bounds__(128) k_out(float* __restrict__ out) {
    __shared__ float4 s2s[4];
    __shared__ float ws[8];
    int g = blockIdx.x;
    int b = blockIdx.y;
    int base = 4 * g - 2;
    int tid = threadIdx.x;

    if (tid < 4)
        s2s[tid] = *(const float4*)(g_S2 + ((size_t)b * LP + 4 * g + tid) * 4);
    __syncthreads();

    if (tid == 0) {
        float w[8];
#pragma unroll
        for (int r = 0; r < 8; r++) w[r] = 0.0f;
#pragma unroll
        for (int lo = 0; lo < 4; lo++) {
            int l = 4 * g + lo;
            float4 s2 = s2s[lo];
            w[l - base] += s2.x * 0.25f;
            { int j0 = l & ~1;      float c = s2.y * (0.25f * 0.5f);
              w[j0 - base] += c; w[j0 + 1 - base] += c; }
            { int j0 = (l / 3) * 3; float c = s2.z * (0.25f / 3.0f);
              w[j0 - base] += c; w[j0 + 1 - base] += c; w[j0 + 2 - base] += c; }
            { int j0 = l & ~3;      float c = s2.w * (0.25f * 0.25f);
              w[j0 - base] += c; w[j0 + 1 - base] += c;
              w[j0 + 2 - base] += c; w[j0 + 3 - base] += c; }
        }
#pragma unroll
        for (int r = 0; r < 8; r++) ws[r] = w[r];
    }
    __syncthreads();

    int d = tid * 4;
    const float* Yb = g_Y2 + ((size_t)b * LP + base) * DM + d;
    float4 acc = {0.0f, 0.0f, 0.0f, 0.0f};
#pragma unroll
    for (int r = 0; r < 8; r++) {
        int row = base + r;
        float wr = ws[r];
        if (row >= 0 && wr != 0.0f) {
            float4 v = *(const float4*)(Yb + (size_t)r * DM);
            acc.x += wr * v.x; acc.y += wr * v.y;
            acc.z += wr * v.z; acc.w += wr * v.w;
        }
    }
    *(float4*)(out + ((size_t)(b * 1024 + g)) * DM + d) = acc;
}

// ---------------- launcher ----------------
extern "C" void kernel_launch(void* const* d_in, const int* in_sizes, int n_in,
                              void* d_out, int out_size) {
    const int*   x   = (const int*)  d_in[0];
    const float* emb = (const float*)d_in[1];
    const float* dww = (const float*)d_in[2];
    const float* dwb = (const float*)d_in[3];
    const float* pww = (const float*)d_in[4];
    const float* pwb = (const float*)d_in[5];
    const float* sw  = (const float*)d_in[6];
    const float* sb  = (const float*)d_in[7];
    float* out = (float*)d_out;

    cudaFuncSetAttribute(k_gemm_mma, cudaFuncAttributeMaxDynamicSharedMemorySize, GEMM_SMEM);

    k_conv<<<dim3(NN / 8, BQ), 128>>>(x, emb, dww, dwb, pww);
    k_gemm_mma<<<dim3(128, 4), 256, GEMM_SMEM>>>(pwb, sw);
    k_scores<<<(NROWS + 255) / 256, 256>>>(sb);
    k_moments<<<dim3(NCHK, BQ), 384>>>();
    k_eval<<<dim3((LP + 127) / 128, BQ), 128>>>();
    k_out<<<dim3(1024, BQ), 128>>>(out);
}

// round 16
// speedup vs baseline: 1.1262x; 1.0122x over previous
#include <cuda_runtime.h>
#include <cuda_bf16.h>
#include <cstdint>

#define BQ 4
#define NN 4096
#define DM 512
#define LP 4104   // ceil(4096/12)*12
#define NROWS (BQ*LP)
#define NMON 330          // monomials of total degree <= 7 in 4 vars
#define MCH 54            // keys per moments chunk
#define NCHK 76           // 76*54 = 4104

// ---------------- scratch (device globals) ----------------
__device__ __nv_bfloat16 g_Yh[(size_t)BQ*NN*DM];   // conv output hi
__device__ __nv_bfloat16 g_Yl[(size_t)BQ*NN*DM];   // conv output lo
__device__ __nv_bfloat16 g_Wh[DM*DM];              // pw_w hi
__device__ __nv_bfloat16 g_Wl[DM*DM];              // pw_w lo
__device__ float g_Y2[(size_t)BQ*LP*DM];           // pointwise output
__device__ float g_T [NROWS];                      // per-position score dot (atomic)
__device__ float g_S2[NROWS*4];                    // attention-mixed scores
__device__ float g_M [BQ][NMON*4];                 // Taylor moments (atomic)
__device__ uchar4 g_MON[NMON];                     // monomial exponents
__device__ float  g_CINV[NMON];                    // 1/prod(a_i!)

// ---------------- block-score softmax from 4 T values ----------------
__device__ __forceinline__ float4 score4_vals(float t0, float t1l, float t1r,
                                              float t2a, float t2b, float t2c,
                                              float t3a, float t3b, float t3c, float t3d) {
    float v0 = t0;
    float v1 = (t1l + t1r) * 0.5f;
    float v2 = (t2a + t2b + t2c) * (1.0f / 3.0f);
    float v3 = (t3a + t3b + t3c + t3d) * 0.25f;
    float mx = fmaxf(fmaxf(v0, v1), fmaxf(v2, v3));
    float e0 = __expf(v0 - mx), e1 = __expf(v1 - mx);
    float e2 = __expf(v2 - mx), e3 = __expf(v3 - mx);
    float inv = 1.0f / (e0 + e1 + e2 + e3);
    return make_float4(e0 * inv, e1 * inv, e2 * inv, e3 * inv);
}
__device__ __forceinline__ float4 score4_g(const float* __restrict__ Tb, int l) {
    int j2 = l & ~1, j3 = (l / 3) * 3, j4 = l & ~3;
    return score4_vals(Tb[l], Tb[j2], Tb[j2 + 1],
                       Tb[j3], Tb[j3 + 1], Tb[j3 + 2],
                       Tb[j4], Tb[j4 + 1], Tb[j4 + 2], Tb[j4 + 3]);
}

// ---------------- conv (+ fused prep: W split, T zero, Y2 pad zero, tables, M zero) ----
__global__ void __launch_bounds__(128) k_conv(const int* __restrict__ x,
                                              const float* __restrict__ emb,
                                              const float* __restrict__ dww,
                                              const float* __restrict__ dwb,
                                              const float* __restrict__ W) {
    int gidx = (blockIdx.y * gridDim.x + blockIdx.x) * 128 + threadIdx.x;
    {
        float w = W[gidx];
        __nv_bfloat16 h = __float2bfloat16(w);
        g_Wh[gidx] = h;
        g_Wl[gidx] = __float2bfloat16(w - __bfloat162float(h));
    }
    if (gidx < NROWS) g_T[gidx] = 0.0f;
    if (gidx < BQ * 8 * DM) {
        int bb = gidx / (8 * DM);
        int r = gidx % (8 * DM);
        g_Y2[((size_t)bb * LP + NN + r / DM) * DM + (r % DM)] = 0.0f;
    }
    if (gidx < BQ * NMON * 4) ((float*)g_M)[gidx] = 0.0f;
    if (gidx < 4096) {   // enumerate monomials: a_i in 0..7, total <= 7
        int a1 = (gidx >> 9) & 7, a2 = (gidx >> 6) & 7;
        int a3 = (gidx >> 3) & 7, a4 = gidx & 7;
        if (a1 + a2 + a3 + a4 <= 7) {
            int r = 0;
            for (int b1 = 0; b1 < a1; b1++) { int m = 7 - b1; r += (m+1)*(m+2)*(m+3)/6; }
            for (int b2 = 0; b2 < a2; b2++) { int m = 7 - a1 - b2; r += (m+1)*(m+2)/2; }
            for (int b3 = 0; b3 < a3; b3++) { int m = 7 - a1 - a2 - b3; r += m + 1; }
            r += a4;
            g_MON[r] = make_uchar4(a1, a2, a3, a4);
            int f1 = 1, f2 = 1, f3 = 1, f4 = 1;
            for (int k = 2; k <= a1; k++) f1 *= k;
            for (int k = 2; k <= a2; k++) f2 *= k;
            for (int k = 2; k <= a3; k++) f3 *= k;
            for (int k = 2; k <= a4; k++) f4 *= k;
            g_CINV[r] = 1.0f / (float)(f1 * f2 * f3 * f4);
        }
    }

    __shared__ float sE[11][DM];
    int t0 = blockIdx.x * 8;
    int b = blockIdx.y;
    int tid = threadIdx.x;

    for (int v = tid; v < 11 * 128; v += 128) {
        int r = v >> 7;
        int c4 = (v & 127) * 4;
        int t = t0 + r;
        float4 e = {0.f, 0.f, 0.f, 0.f};
        if (t < NN) {
            int id = x[b * NN + t];
            e = *(const float4*)(emb + (size_t)id * DM + c4);
        }
        *(float4*)(&sE[r][c4]) = e;
    }
    __syncthreads();

    int d0 = tid * 4;
    float w[4][4];
#pragma unroll
    for (int j = 0; j < 4; j++) {
        float4 wv = *(const float4*)(dww + (d0 + j) * 4);
        w[j][0] = wv.x; w[j][1] = wv.y; w[j][2] = wv.z; w[j][3] = wv.w;
    }
    float4 bb = *(const float4*)(dwb + d0);

#pragma unroll
    for (int tok = 0; tok < 8; tok++) {
        float acc[4] = {bb.x, bb.y, bb.z, bb.w};
#pragma unroll
        for (int k = 0; k < 4; k++) {
            float4 e = *(const float4*)(&sE[tok + k][d0]);
            acc[0] += e.x * w[0][k];
            acc[1] += e.y * w[1][k];
            acc[2] += e.z * w[2][k];
            acc[3] += e.w * w[3][k];
        }
        size_t base = ((size_t)(b * NN + t0 + tok)) * DM + d0;
        __nv_bfloat16 h[4], l[4];
#pragma unroll
        for (int j = 0; j < 4; j++) {
            h[j] = __float2bfloat16(acc[j]);
            l[j] = __float2bfloat16(acc[j] - __bfloat162float(h[j]));
        }
        __nv_bfloat162* ph = (__nv_bfloat162*)(g_Yh + base);
        __nv_bfloat162* pl = (__nv_bfloat162*)(g_Yl + base);
        ph[0] = __halves2bfloat162(h[0], h[1]);
        ph[1] = __halves2bfloat162(h[2], h[3]);
        pl[0] = __halves2bfloat162(l[0], l[1]);
        pl[1] = __halves2bfloat162(l[2], l[3]);
    }
}

// ---------------- HMMA GEMM: Y2 = Y @ W^T + bias, bf16x3, cp.async 3-stage ----------------
#define TILE_B 8192
#define STAGE_B (4*TILE_B)
#define GEMM_SMEM (3*STAGE_B)

__device__ __forceinline__ uint32_t swz(uint32_t row, uint32_t chunk) {
    return row * 64 + ((chunk ^ ((row >> 1) & 3)) << 4);
}
__device__ __forceinline__ void ldsm4(uint32_t* r, uint32_t addr) {
    asm volatile("ldmatrix.sync.aligned.m8n8.x4.shared.b16 {%0,%1,%2,%3}, [%4];"
                 : "=r"(r[0]), "=r"(r[1]), "=r"(r[2]), "=r"(r[3]) : "r"(addr));
}
__device__ __forceinline__ void mma16816(float* c, const uint32_t* a, const uint32_t* b) {
    asm volatile(
        "mma.sync.aligned.m16n8k16.row.col.f32.bf16.bf16.f32 "
        "{%0,%1,%2,%3}, {%4,%5,%6,%7}, {%8,%9}, {%0,%1,%2,%3};"
        : "+f"(c[0]), "+f"(c[1]), "+f"(c[2]), "+f"(c[3])
        : "r"(a[0]), "r"(a[1]), "r"(a[2]), "r"(a[3]), "r"(b[0]), "r"(b[1]));
}
__device__ __forceinline__ void cpa16(uint32_t dst, const void* src) {
    asm volatile("cp.async.cg.shared.global [%0], [%1], 16;" :: "r"(dst), "l"(src));
}

__global__ void __launch_bounds__(256, 2) k_gemm_mma(const float* __restrict__ bias,
                                                     const float* __restrict__ sw) {
    extern __shared__ char sm[];
    uint32_t smu = (uint32_t)__cvta_generic_to_shared(sm);

    int tid = threadIdx.x, wid = tid >> 5, lane = tid & 31;
    int warp_m = wid & 1;
    int warp_n = wid >> 1;
    int mtile = blockIdx.x;
    int bn = blockIdx.y;

    const __nv_bfloat16* gA[2] = {g_Yh + (size_t)mtile * 128 * DM,
                                  g_Yl + (size_t)mtile * 128 * DM};
    const __nv_bfloat16* gB[2] = {g_Wh + (size_t)bn * 128 * DM,
                                  g_Wl + (size_t)bn * 128 * DM};

    int r0 = tid >> 2, cc0 = tid & 3;
    int r1 = r0 + 64;
    uint32_t so0 = swz(r0, cc0);
    uint32_t so1 = swz(r1, cc0);

    auto load_stage = [&](int kc, int stage) {
        uint32_t base = smu + stage * STAGE_B;
        size_t go0 = (size_t)r0 * DM + kc * 32 + cc0 * 8;
        size_t go1 = (size_t)r1 * DM + kc * 32 + cc0 * 8;
#pragma unroll
        for (int p = 0; p < 2; p++) {
            cpa16(base + p * TILE_B + so0, gA[p] + go0);
            cpa16(base + p * TILE_B + so1, gA[p] + go1);
            cpa16(base + (2 + p) * TILE_B + so0, gB[p] + go0);
            cpa16(base + (2 + p) * TILE_B + so1, gB[p] + go1);
        }
        asm volatile("cp.async.commit_group;");
    };

    float c[4][4][4];
#pragma unroll
    for (int mt = 0; mt < 4; mt++)
#pragma unroll
        for (int nt = 0; nt < 4; nt++)
#pragma unroll
            for (int e = 0; e < 4; e++) c[mt][nt][e] = 0.0f;

    int lr = lane & 7, g = lane >> 3;
    int a_row = (g & 1) * 8 + lr;
    int a_kc8 = (g >> 1);
    int b_nrw = (g >> 1) * 8 + lr;
    int b_kc8 = (g & 1);

    load_stage(0, 0);
    load_stage(1, 1);

    for (int kc = 0; kc < 16; kc++) {
        if (kc + 1 < 16) asm volatile("cp.async.wait_group 1;");
        else             asm volatile("cp.async.wait_group 0;");
        __syncthreads();
        if (kc + 2 < 16) load_stage(kc + 2, (kc + 2) % 3);

        uint32_t sAh = smu + (kc % 3) * STAGE_B;
        uint32_t sAl = sAh + TILE_B;
        uint32_t sBh = sAh + 2 * TILE_B;
        uint32_t sBl = sAh + 3 * TILE_B;

#pragma unroll
        for (int ks = 0; ks < 2; ks++) {
            uint32_t bh[8], bl[8], a[4][4];
#pragma unroll
            for (int hh = 0; hh < 2; hh++) {
                uint32_t row = warp_n * 32 + hh * 16 + b_nrw;
                uint32_t off = swz(row, 2 * ks + b_kc8);
                ldsm4(bh + hh * 4, sBh + off);
                ldsm4(bl + hh * 4, sBl + off);
            }
#pragma unroll
            for (int mt = 0; mt < 4; mt++) {
                uint32_t row = warp_m * 64 + mt * 16 + a_row;
                uint32_t off = swz(row, 2 * ks + a_kc8);
                ldsm4(a[mt], sAh + off);
            }
#pragma unroll
            for (int mt = 0; mt < 4; mt++)
#pragma unroll
                for (int nt = 0; nt < 4; nt++) {
                    int bi = (nt >> 1) * 4 + (nt & 1) * 2;
                    uint32_t b0[2] = {bh[bi], bh[bi + 1]};
                    mma16816(c[mt][nt], a[mt], b0);
                    uint32_t b1[2] = {bl[bi], bl[bi + 1]};
                    mma16816(c[mt][nt], a[mt], b1);
                }
#pragma unroll
            for (int mt = 0; mt < 4; mt++) {
                uint32_t row = warp_m * 64 + mt * 16 + a_row;
                uint32_t off = swz(row, 2 * ks + a_kc8);
                ldsm4(a[mt], sAl + off);
            }
#pragma unroll
            for (int mt = 0; mt < 4; mt++)
#pragma unroll
                for (int nt = 0; nt < 4; nt++) {
                    int bi = (nt >> 1) * 4 + (nt & 1) * 2;
                    uint32_t b0[2] = {bh[bi], bh[bi + 1]};
                    mma16816(c[mt][nt], a[mt], b0);
                }
        }
    }

    float tp[4][2];
#pragma unroll
    for (int mt = 0; mt < 4; mt++) { tp[mt][0] = 0.0f; tp[mt][1] = 0.0f; }

#pragma unroll
    for (int mt = 0; mt < 4; mt++) {
        int row0 = mtile * 128 + warp_m * 64 + mt * 16 + (lane >> 2);
        int row1 = row0 + 8;
        int b0i = row0 >> 12, l0i = row0 & 4095;
        int b1i = row1 >> 12, l1i = row1 & 4095;
        float* o0 = g_Y2 + ((size_t)b0i * LP + l0i) * DM;
        float* o1 = g_Y2 + ((size_t)b1i * LP + l1i) * DM;
#pragma unroll
        for (int nt = 0; nt < 4; nt++) {
            int col = bn * 128 + warp_n * 32 + nt * 8 + 2 * (lane & 3);
            float bi0 = bias[col], bi1 = bias[col + 1];
            float s0 = sw[col], s1 = sw[col + 1];
            float v00 = c[mt][nt][0] + bi0, v01 = c[mt][nt][1] + bi1;
            float v10 = c[mt][nt][2] + bi0, v11 = c[mt][nt][3] + bi1;
            tp[mt][0] += v00 * s0 + v01 * s1;
            tp[mt][1] += v10 * s0 + v11 * s1;
            float2 w0 = {v00, v01}, w1 = {v10, v11};
            *(float2*)(o0 + col) = w0;
            *(float2*)(o1 + col) = w1;
        }
    }
#pragma unroll
    for (int mt = 0; mt < 4; mt++) {
#pragma unroll
        for (int rs = 0; rs < 2; rs++) {
            float r = tp[mt][rs];
            r += __shfl_xor_sync(0xffffffff, r, 1);
            r += __shfl_xor_sync(0xffffffff, r, 2);
            if ((lane & 3) == 0) {
                int row = mtile * 128 + warp_m * 64 + mt * 16 + rs * 8 + (lane >> 2);
                int bb = row >> 12, ll = row & 4095;
                atomicAdd(&g_T[bb * LP + ll], r);
            }
        }
    }
}

// ---------------- Taylor moments (+ fused key-score softmax) ----------------
__global__ void __launch_bounds__(384) k_moments() {
    __shared__ float sT[MCH + 8];         // T window with +-3 halo
    __shared__ float sPow[4 * 8 * MCH];   // (i*8+e)*MCH + j
    int b = blockIdx.y, ch = blockIdx.x;
    int tid = threadIdx.x;
    const float* Tb = g_T + (size_t)b * LP;
    int s0i = ch * MCH;
    int w0 = s0i - 3;

    if (tid < MCH + 6) {
        int t = w0 + tid;
        sT[tid] = (t >= 0 && t < LP) ? Tb[t] : 0.0f;
    }
    __syncthreads();

    if (tid < MCH) {
        int l = s0i + tid;
        int j2 = l & ~1, j3 = (l / 3) * 3, j4 = l & ~3;
        float4 s = score4_vals(sT[l - w0], sT[j2 - w0], sT[j2 + 1 - w0],
                               sT[j3 - w0], sT[j3 + 1 - w0], sT[j3 + 2 - w0],
                               sT[j4 - w0], sT[j4 + 1 - w0], sT[j4 + 2 - w0], sT[j4 + 3 - w0]);
        float comp[4] = {s.x, s.y, s.z, s.w};
#pragma unroll
        for (int i = 0; i < 4; i++) {
            float p = 1.0f;
#pragma unroll
            for (int e = 0; e < 8; e++) {
                sPow[(i * 8 + e) * MCH + tid] = p;
                p *= comp[i];
            }
        }
    }
    __syncthreads();

    if (tid < NMON) {
        uchar4 a = g_MON[tid];
        float c = g_CINV[tid];
        const float* p0 = sPow + (0 * 8 + a.x) * MCH;
        const float* p1 = sPow + (1 * 8 + a.y) * MCH;
        const float* p2 = sPow + (2 * 8 + a.z) * MCH;
        const float* p3 = sPow + (3 * 8 + a.w) * MCH;
        const float* s0 = sPow + 1 * MCH;
        const float* s1 = sPow + 9 * MCH;
        const float* s2 = sPow + 17 * MCH;
        const float* s3 = sPow + 25 * MCH;
        float acc0 = 0.f, acc1 = 0.f, acc2 = 0.f, acc3 = 0.f;
#pragma unroll 6
        for (int j = 0; j < MCH; j++) {
            float v = p0[j] * p1[j] * p2[j] * p3[j];
            acc0 += v * s0[j];
            acc1 += v * s1[j];
            acc2 += v * s2[j];
            acc3 += v * s3[j];
        }
        atomicAdd(&g_M[b][tid * 4 + 0], acc0 * c);
        atomicAdd(&g_M[b][tid * 4 + 1], acc1 * c);
        atomicAdd(&g_M[b][tid * 4 + 2], acc2 * c);
        atomicAdd(&g_M[b][tid * 4 + 3], acc3 * c);
    }
}

// ---------------- eval (+ fused query-score): S2(q) = N/z ----------------
__global__ void __launch_bounds__(128) k_eval() {
    __shared__ float sM[NMON * 4];
    __shared__ uchar4 sMON[NMON];
    __shared__ float qp[128 * 33];
    int b = blockIdx.y;
    int tid = threadIdx.x;
    int i0 = blockIdx.x * 128 + tid;
    const float* Tb = g_T + (size_t)b * LP;

    for (int t = tid; t < NMON * 4; t += 128) sM[t] = g_M[b][t];
    for (int t = tid; t < NMON; t += 128) sMON[t] = g_MON[t];

    float4 q = {0.f, 0.f, 0.f, 0.f};
    if (i0 < LP) q = score4_g(Tb, i0);
    {
        float comp[4] = {q.x, q.y, q.z, q.w};
        int base = tid * 33;
#pragma unroll
        for (int i = 0; i < 4; i++) {
            float p = 1.0f;
#pragma unroll
            for (int e = 0; e < 8; e++) {
                qp[base + i * 8 + e] = p;
                p *= comp[i];
            }
        }
    }
    __syncthreads();

    int base = tid * 33;
    float a0 = 0.f, a1 = 0.f, a2 = 0.f, a3 = 0.f;
#pragma unroll 2
    for (int m = 0; m < NMON; m++) {
        uchar4 a = sMON[m];
        float v = qp[base + a.x] * qp[base + 8 + a.y]
                * qp[base + 16 + a.z] * qp[base + 24 + a.w];
        float4 Mv = *(const float4*)(&sM[m * 4]);
        a0 = fmaf(v, Mv.x, a0);
        a1 = fmaf(v, Mv.y, a1);
        a2 = fmaf(v, Mv.z, a2);
        a3 = fmaf(v, Mv.w, a3);
    }
    if (i0 < LP) {
        float inv = 1.0f / (a0 + a1 + a2 + a3);
        float4 r = {a0 * inv, a1 * inv, a2 * inv, a3 * inv};
        *(float4*)(g_S2 + ((size_t)b * LP + i0) * 4) = r;
    }
}

// ---------------- output: one-thread weight build + pooled store ----------
__global__ void __launch_bounds__(128) k_out(float* __restrict__ out) {
    __shared__ float4 s2s[4];
    __shared__ float ws[8];
    int g = blockIdx.x;
    int b = blockIdx.y;
    int base = 4 * g - 2;
    int tid = threadIdx.x;

    if (tid < 4)
        s2s[tid] = *(const float4*)(g_S2 + ((size_t)b * LP + 4 * g + tid) * 4);
    __syncthreads();

    if (tid == 0) {
        float w[8];
#pragma unroll
        for (int r = 0; r < 8; r++) w[r] = 0.0f;
#pragma unroll
        for (int lo = 0; lo < 4; lo++) {
            int l = 4 * g + lo;
            float4 s2 = s2s[lo];
            w[l - base] += s2.x * 0.25f;
            { int j0 = l & ~1;      float c = s2.y * (0.25f * 0.5f);
              w[j0 - base] += c; w[j0 + 1 - base] += c; }
            { int j0 = (l / 3) * 3; float c = s2.z * (0.25f / 3.0f);
              w[j0 - base] += c; w[j0 + 1 - base] += c; w[j0 + 2 - base] += c; }
            { int j0 = l & ~3;      float c = s2.w * (0.25f * 0.25f);
              w[j0 - base] += c; w[j0 + 1 - base] += c;
              w[j0 + 2 - base] += c; w[j0 + 3 - base] += c; }
        }
#pragma unroll
        for (int r = 0; r < 8; r++) ws[r] = w[r];
    }
    __syncthreads();

    int d = tid * 4;
    const float* Yb = g_Y2 + ((size_t)b * LP + base) * DM + d;
    float4 acc = {0.0f, 0.0f, 0.0f, 0.0f};
#pragma unroll
    for (int r = 0; r < 8; r++) {
        int row = base + r;
        float wr = ws[r];
        if (row >= 0 && wr != 0.0f) {
            float4 v = *(const float4*)(Yb + (size_t)r * DM);
            acc.x += wr * v.x; acc.y += wr * v.y;
            acc.z += wr * v.z; acc.w += wr * v.w;
        }
    }
    *(float4*)(out + ((size_t)(b * 1024 + g)) * DM + d) = acc;
}

// ---------------- launcher ----------------
extern "C" void kernel_launch(void* const* d_in, const int* in_sizes, int n_in,
                              void* d_out, int out_size) {
    const int*   x   = (const int*)  d_in[0];
    const float* emb = (const float*)d_in[1];
    const float* dww = (const float*)d_in[2];
    const float* dwb = (const float*)d_in[3];
    const float* pww = (const float*)d_in[4];
    const float* pwb = (const float*)d_in[5];
    const float* sw  = (const float*)d_in[6];
    const float* sb  = (const float*)d_in[7];
    float* out = (float*)d_out;

    cudaFuncSetAttribute(k_gemm_mma, cudaFuncAttributeMaxDynamicSharedMemorySize, GEMM_SMEM);

    k_conv<<<dim3(NN / 8, BQ), 128>>>(x, emb, dww, dwb, pww);
    k_gemm_mma<<<dim3(128, 4), 256, GEMM_SMEM>>>(pwb, sw);
    k_moments<<<dim3(NCHK, BQ), 384>>>();
    k_eval<<<dim3((LP + 127) / 128, BQ), 128>>>();
    k_out<<<dim3(1024, BQ), 128>>>(out);
}